// round 6
// baseline (speedup 1.0000x reference)
#include <cuda_runtime.h>

// y[b,c] = b_fc[c] + sum_f h[b,0,f] * V[c,f],  V = W_fc @ W_emb  ([2,768])
// (TreeLSTM scan in the reference is dead code; adj and recurrent weights unused.)
// B=32, N=128, FI=768, FO=128.
//
// Single launch, 24 independent blocks, each owning a 32-wide f-slice.
// Partial y accumulated via atomicAdd into device scratch; the LAST block to
// finish (atomic ticket, no spinning) writes d_out and resets the scratch.

#define B_   32
#define N_   128
#define FI_  768
#define FO_  128
#define NBLK 24

__device__ float    g_acc[64];     // zero-init at load; reset by last block each run
__device__ unsigned g_cnt = 0;

__global__ __launch_bounds__(256, 1)
void rvnn_onekernel(const float* __restrict__ h,      // [B,N,FI]
                    const float* __restrict__ W_emb,  // [FO,FI]
                    const float* __restrict__ W_fc,   // [2,FO]
                    const float* __restrict__ b_fc,   // [2]
                    float* __restrict__ y)            // [B,2]
{
    const int t    = threadIdx.x;
    const int fl   = t & 31;       // f within slice
    const int og   = t >> 5;       // o-chunk 0..7 (16 o's each)
    const int base = blockIdx.x * 32;

    __shared__ float s_wfc[2 * FO_];
    __shared__ float sp0[8][32], sp1[8][32];
    __shared__ float s_h[B_][33];        // padded: no bank conflicts in phase 2
    __shared__ float s_V[2][33];

    // ---- Front-batch ALL global loads (one latency round) ----
    float w[16];
    const float* wp = W_emb + (size_t)(og * 16) * FI_ + base + fl;
    #pragma unroll
    for (int j = 0; j < 16; ++j)
        w[j] = __ldg(wp + (size_t)j * FI_);          // 128B coalesced per warp

    float hv[4];
    #pragma unroll
    for (int r = 0; r < 4; ++r) {
        const int idx = r * 256 + t;                  // 0..1023
        const int b = idx >> 5, f = idx & 31;
        hv[r] = __ldg(&h[(size_t)b * N_ * FI_ + base + f]);  // warp = one b row chunk
    }

    s_wfc[t] = __ldg(&W_fc[t]);                       // 256 floats exactly

    // Stage h slice while loads drain.
    #pragma unroll
    for (int r = 0; r < 4; ++r) {
        const int idx = r * 256 + t;
        s_h[idx >> 5][idx & 31] = hv[r];
    }
    __syncthreads();

    // ---- Phase 1: partial V over this thread's 16 o's ----
    float a0 = 0.0f, a1 = 0.0f;
    #pragma unroll
    for (int j = 0; j < 16; ++j) {
        const int o = og * 16 + j;
        a0 = fmaf(s_wfc[o],       w[j], a0);
        a1 = fmaf(s_wfc[FO_ + o], w[j], a1);
    }
    sp0[og][fl] = a0;
    sp1[og][fl] = a1;
    __syncthreads();

    if (t < 32) {
        float s = 0.0f;
        #pragma unroll
        for (int k = 0; k < 8; ++k) s += sp0[k][t];
        s_V[0][t] = s;
    } else if (t < 64) {
        const int l = t - 32;
        float s = 0.0f;
        #pragma unroll
        for (int k = 0; k < 8; ++k) s += sp1[k][l];
        s_V[1][l] = s;
    }
    __syncthreads();

    // ---- Phase 2: partial y[b,c] over this f-slice, atomic accumulate ----
    if (t < 64) {
        const int b = t >> 1, c = t & 1;
        float acc = 0.0f;
        #pragma unroll
        for (int f = 0; f < 32; ++f)
            acc = fmaf(s_h[b][f], s_V[c][f], acc);
        atomicAdd(&g_acc[t], acc);
        __threadfence();                  // make this thread's add visible
    }
    __syncthreads();

    // ---- Last block finalizes (no spinning anywhere) ----
    if (t == 0) {
        const unsigned prev = atomicAdd(&g_cnt, 1u);
        if (prev == NBLK - 1) {
            __threadfence();              // acquire: see all g_acc adds
            const float bf0 = b_fc[0], bf1 = b_fc[1];
            #pragma unroll
            for (int i = 0; i < 64; i += 2) {
                float v0 = g_acc[i], v1 = g_acc[i + 1];
                y[i]     = v0 + bf0;
                y[i + 1] = v1 + bf1;
                g_acc[i] = 0.0f;          // reset for next replay
                g_acc[i + 1] = 0.0f;
            }
            g_cnt = 0u;
        }
    }
}

extern "C" void kernel_launch(void* const* d_in, const int* in_sizes, int n_in,
                              void* d_out, int out_size)
{
    // metadata order: h, adj, W_emb, W_ioux, b_ioux, W_iouh, b_iouh,
    //                 W_coux, b_coux, W_couh, b_couh, W_fc, b_fc
    const float* h     = (const float*)d_in[0];
    const float* W_emb = (const float*)d_in[2];
    const float* W_fc  = (const float*)d_in[11];
    const float* b_fc  = (const float*)d_in[12];
    float* y = (float*)d_out;

    rvnn_onekernel<<<NBLK, 256>>>(h, W_emb, W_fc, b_fc, y);
}

// round 7
// speedup vs baseline: 2.5288x; 2.5288x over previous
#include <cuda_runtime.h>

// y[b,c] = b_fc[c] + dot(h[b,0,:], V[c,:]),  V = W_fc @ W_emb  ([2,768])
// (TreeLSTM scan in the reference is dead code; adj and recurrent weights unused.)
// B=32, N=128, FI=768, FO=128.
//
// Two kernels with Programmatic Dependent Launch: B launches while A streams
// W_emb; B preloads h, then cudaGridDependencySynchronize() before touching V.

#define B_  32
#define N_  128
#define FI_ 768
#define FO_ 128

__device__ float g_V[2][FI_];   // scratch: V = W_fc @ W_emb

// ---- Kernel A: V[c,f] = sum_o W_fc[c,o] * W_emb[o,f] ----
// 24 blocks x 256 threads; block owns 32 f-columns; 8 warps split o (16 each).
__global__ __launch_bounds__(256, 1)
void rvnn_precompute_V(const float* __restrict__ W_emb,  // [FO,FI]
                       const float* __restrict__ W_fc)   // [2,FO]
{
    // Let the dependent kernel launch immediately.
    cudaTriggerProgrammaticLaunchCompletion();

    const int t  = threadIdx.x;
    const int fl = t & 31;        // f within block
    const int g  = t >> 5;        // o-chunk 0..7
    const int f  = blockIdx.x * 32 + fl;

    float a0 = 0.0f, a1 = 0.0f;
    #pragma unroll
    for (int j = 0; j < 16; ++j) {
        const int o = g * 16 + j;
        float w = __ldg(&W_emb[(size_t)o * FI_ + f]);   // coalesced across lanes
        a0 = fmaf(__ldg(&W_fc[o]),       w, a0);
        a1 = fmaf(__ldg(&W_fc[FO_ + o]), w, a1);
    }

    __shared__ float sp0[8][32], sp1[8][32];
    sp0[g][fl] = a0;
    sp1[g][fl] = a1;
    __syncthreads();

    if (t < 32) {
        float s = 0.0f;
        #pragma unroll
        for (int k = 0; k < 8; ++k) s += sp0[k][t];
        g_V[0][blockIdx.x * 32 + t] = s;
    } else if (t < 64) {
        const int l = t - 32;
        float s = 0.0f;
        #pragma unroll
        for (int k = 0; k < 8; ++k) s += sp1[k][l];
        g_V[1][blockIdx.x * 32 + l] = s;
    }
}

// ---- Kernel B: y[b,c] = b_fc[c] + dot(h[b,0,:], V[c,:]) ----
// 32 blocks x 192 threads. Preload h, griddepsync, then consume V.
__global__ __launch_bounds__(192, 1)
void rvnn_head_kernel(const float* __restrict__ h,    // [B,N,FI]
                      const float* __restrict__ b_fc, // [2]
                      float* __restrict__ y)          // [B,2]
{
    const int b    = blockIdx.x;
    const int t    = threadIdx.x;           // 0..191
    const int warp = t >> 5;                // 0..5
    const int lane = t & 31;

    // h loads issue while kernel A is still running (PDL overlap).
    const float4* hrow = reinterpret_cast<const float4*>(h + (size_t)b * N_ * FI_);
    float4 hv = __ldg(&hrow[t]);

    // Wait until kernel A's g_V writes are visible.
    cudaGridDependencySynchronize();

    float4 v0 = *reinterpret_cast<const float4*>(&g_V[0][t * 4]);
    float4 v1 = *reinterpret_cast<const float4*>(&g_V[1][t * 4]);

    float a0 = fmaf(hv.x, v0.x, fmaf(hv.y, v0.y, fmaf(hv.z, v0.z, hv.w * v0.w)));
    float a1 = fmaf(hv.x, v1.x, fmaf(hv.y, v1.y, fmaf(hv.z, v1.z, hv.w * v1.w)));

    #pragma unroll
    for (int off = 16; off > 0; off >>= 1) {
        a0 += __shfl_down_sync(0xffffffffu, a0, off);
        a1 += __shfl_down_sync(0xffffffffu, a1, off);
    }

    __shared__ float w0[6], w1[6];
    if (lane == 0) { w0[warp] = a0; w1[warp] = a1; }
    __syncthreads();

    if (t == 0) {
        float s0 = w0[0] + w0[1] + w0[2] + w0[3] + w0[4] + w0[5];
        float s1 = w1[0] + w1[1] + w1[2] + w1[3] + w1[4] + w1[5];
        y[b * 2 + 0] = s0 + b_fc[0];
        y[b * 2 + 1] = s1 + b_fc[1];
    }
}

extern "C" void kernel_launch(void* const* d_in, const int* in_sizes, int n_in,
                              void* d_out, int out_size)
{
    // metadata order: h, adj, W_emb, W_ioux, b_ioux, W_iouh, b_iouh,
    //                 W_coux, b_coux, W_couh, b_couh, W_fc, b_fc
    const float* h     = (const float*)d_in[0];
    const float* W_emb = (const float*)d_in[2];
    const float* W_fc  = (const float*)d_in[11];
    const float* b_fc  = (const float*)d_in[12];
    float* y = (float*)d_out;

    rvnn_precompute_V<<<FI_ / 32, 256>>>(W_emb, W_fc);

    // Kernel B with Programmatic Dependent Launch: may start while A runs.
    cudaLaunchConfig_t cfg = {};
    cfg.gridDim  = dim3(B_, 1, 1);
    cfg.blockDim = dim3(192, 1, 1);
    cfg.dynamicSmemBytes = 0;
    cfg.stream = 0;  // legacy default stream (same one the harness captures)
    cudaLaunchAttribute attrs[1];
    attrs[0].id = cudaLaunchAttributeProgrammaticStreamSerialization;
    attrs[0].val.programmaticStreamSerializationAllowed = 1;
    cfg.attrs = attrs;
    cfg.numAttrs = 1;
    cudaLaunchKernelEx(&cfg, rvnn_head_kernel, h, b_fc, y);
}